// round 1
// baseline (speedup 1.0000x reference)
#include <cuda_runtime.h>
#include <math.h>

#define NB 8
#define NN 2048
#define DD 128
#define ROWS_TOT (NB * NN)

// Scratch (no allocations allowed anywhere)
__device__ float g_bufA[ROWS_TOT * DD];   // h after linear (fused input)
__device__ float g_bufB[ROWS_TOT * DD];   // aggregation output (next layer input)
__device__ float g_rn[ROWS_TOT];          // 1 / max(||h_row||, 1e-12)

#define SMEM_LIN   ((64 * 132 + 128 * 132) * 4)
#define SMEM_FUSED ((64 * 132 * 2 + 64 * 68 + 64) * 4)

// ---------------------------------------------------------------------------
// Linear + bias + reciprocal row norm.
// Block: 256 threads, 64 rows. W (128x128) staged in smem once per block.
// Thread (tx,ty) in 16x16 grid: rows ty*4..+3, cols tx + 16*j (j<8).
// ---------------------------------------------------------------------------
__global__ __launch_bounds__(256, 2) void linear_norm_kernel(
    const float* __restrict__ in,    // [ROWS, 128]
    const float* __restrict__ W,     // [128, 128]
    const float* __restrict__ bias,  // [128]
    float* __restrict__ hout,        // [ROWS, 128]
    float* __restrict__ rn)          // [ROWS]
{
    extern __shared__ float sm[];
    float* sx = sm;            // 64 x 132 (padded)
    float* sw = sm + 64 * 132; // 128 x 132 (padded)

    const int t = threadIdx.x;
    const int rowbase = blockIdx.x * 64;
    const int f4 = (t & 31) * 4;
    const int r0 = t >> 5;

    #pragma unroll
    for (int r = r0; r < 64; r += 8)
        *(float4*)&sx[r * 132 + f4] = *(const float4*)&in[(size_t)(rowbase + r) * DD + f4];
    #pragma unroll
    for (int r = r0; r < 128; r += 8)
        *(float4*)&sw[r * 132 + f4] = *(const float4*)&W[(size_t)r * DD + f4];
    __syncthreads();

    const int tx = t & 15;
    const int ty = t >> 4;

    float acc[4][8];
    #pragma unroll
    for (int i = 0; i < 4; i++)
        #pragma unroll
        for (int j = 0; j < 8; j++) acc[i][j] = 0.0f;

    #pragma unroll 4
    for (int k = 0; k < DD; k++) {
        float a[4], w[8];
        #pragma unroll
        for (int i = 0; i < 4; i++) a[i] = sx[(ty * 4 + i) * 132 + k];
        #pragma unroll
        for (int j = 0; j < 8; j++) w[j] = sw[k * 132 + tx + 16 * j];
        #pragma unroll
        for (int i = 0; i < 4; i++)
            #pragma unroll
            for (int j = 0; j < 8; j++)
                acc[i][j] = fmaf(a[i], w[j], acc[i][j]);
    }

    float bv[8];
    #pragma unroll
    for (int j = 0; j < 8; j++) bv[j] = bias[tx + 16 * j];

    #pragma unroll
    for (int i = 0; i < 4; i++) {
        float ss = 0.0f;
        #pragma unroll
        for (int j = 0; j < 8; j++) {
            acc[i][j] += bv[j];
            ss = fmaf(acc[i][j], acc[i][j], ss);
        }
        // rows live on 16 contiguous lanes (same ty) -> segment reduce
        #pragma unroll
        for (int off = 8; off > 0; off >>= 1)
            ss += __shfl_xor_sync(0xffffffffu, ss, off, 16);
        if (tx == 0)
            rn[rowbase + ty * 4 + i] = 1.0f / fmaxf(sqrtf(ss), 1e-12f);
    }

    #pragma unroll
    for (int i = 0; i < 4; i++)
        #pragma unroll
        for (int j = 0; j < 8; j++)
            hout[(size_t)(rowbase + ty * 4 + i) * DD + tx + 16 * j] = acc[i][j];
}

// ---------------------------------------------------------------------------
// Fused: out[p,:] = sum_q ew[p,q] * rn_p*rn_q*(h_p . h_q) * h[q,:]
// Block: 256 threads, 64 p-rows per block. Loop q in tiles of 64.
// Phase1: S = h_p @ h_q^T (4x4 register microtile, float4 over k)
// Phase2: S *= rn_p*rn_q*ew (coalesced float4 ew loads)
// Phase3: O += S @ h_q (4 rows x 8 cols per thread, cols = tx*8..+7)
// ---------------------------------------------------------------------------
__global__ __launch_bounds__(256, 2) void fused_agg_kernel(
    const float* __restrict__ h,    // [B*N, 128]
    const float* __restrict__ rn,   // [B*N]
    const float* __restrict__ ew,   // [B, N, N]
    float* __restrict__ out,        // [B*N, 128]
    int do_relu)
{
    extern __shared__ float sm[];
    float* shp = sm;                 // 64 x 132
    float* shq = shp + 64 * 132;     // 64 x 132
    float* sS  = shq + 64 * 132;     // 64 x 68
    float* srq = sS + 64 * 68;       // 64

    const int t = threadIdx.x;
    const int tx = t & 15;
    const int ty = t >> 4;
    const int b = blockIdx.y;
    const int pbase = blockIdx.x * 64;

    const float* hB  = h + (size_t)b * NN * DD;
    const float* rnB = rn + (size_t)b * NN;
    const float* ewB = ew + (size_t)b * NN * NN;

    const int f4 = (t & 31) * 4;
    const int r0 = t >> 5;

    // p tile: loaded once
    #pragma unroll
    for (int r = r0; r < 64; r += 8)
        *(float4*)&shp[r * 132 + f4] = *(const float4*)&hB[(size_t)(pbase + r) * DD + f4];

    float rp[4];
    #pragma unroll
    for (int i = 0; i < 4; i++) rp[i] = rnB[pbase + ty * 4 + i];

    float o[4][8];
    #pragma unroll
    for (int i = 0; i < 4; i++)
        #pragma unroll
        for (int j = 0; j < 8; j++) o[i][j] = 0.0f;

    for (int qb = 0; qb < NN; qb += 64) {
        __syncthreads();  // prev phase3 done with shq/sS
        #pragma unroll
        for (int r = r0; r < 64; r += 8)
            *(float4*)&shq[r * 132 + f4] = *(const float4*)&hB[(size_t)(qb + r) * DD + f4];
        if (t < 64) srq[t] = rnB[qb + t];
        __syncthreads();

        // ---- phase 1: raw dot products S[4][4] ----
        float s[4][4];
        #pragma unroll
        for (int i = 0; i < 4; i++)
            #pragma unroll
            for (int j = 0; j < 4; j++) s[i][j] = 0.0f;

        #pragma unroll 2
        for (int k = 0; k < DD; k += 4) {
            float4 ap[4], bq[4];
            #pragma unroll
            for (int i = 0; i < 4; i++)
                ap[i] = *(const float4*)&shp[(ty * 4 + i) * 132 + k];
            #pragma unroll
            for (int j = 0; j < 4; j++)
                bq[j] = *(const float4*)&shq[(tx * 4 + j) * 132 + k];
            #pragma unroll
            for (int i = 0; i < 4; i++)
                #pragma unroll
                for (int j = 0; j < 4; j++) {
                    s[i][j] = fmaf(ap[i].x, bq[j].x, s[i][j]);
                    s[i][j] = fmaf(ap[i].y, bq[j].y, s[i][j]);
                    s[i][j] = fmaf(ap[i].z, bq[j].z, s[i][j]);
                    s[i][j] = fmaf(ap[i].w, bq[j].w, s[i][j]);
                }
        }

        // ---- phase 2: mask with rn_p * rn_q * ew ----
        float rq[4];
        #pragma unroll
        for (int j = 0; j < 4; j++) rq[j] = srq[tx * 4 + j];
        #pragma unroll
        for (int i = 0; i < 4; i++) {
            const float4 e = *(const float4*)&ewB[(size_t)(pbase + ty * 4 + i) * NN + qb + tx * 4];
            const float rpi = rp[i];
            s[i][0] *= rpi * rq[0] * e.x;
            s[i][1] *= rpi * rq[1] * e.y;
            s[i][2] *= rpi * rq[2] * e.z;
            s[i][3] *= rpi * rq[3] * e.w;
            *(float4*)&sS[(ty * 4 + i) * 68 + tx * 4] =
                make_float4(s[i][0], s[i][1], s[i][2], s[i][3]);
        }
        __syncthreads();

        // ---- phase 3: O += S @ h_q ----
        #pragma unroll 4
        for (int k = 0; k < 64; k++) {
            float a[4];
            #pragma unroll
            for (int i = 0; i < 4; i++) a[i] = sS[(ty * 4 + i) * 68 + k];
            const float4 h0 = *(const float4*)&shq[k * 132 + tx * 8];
            const float4 h1 = *(const float4*)&shq[k * 132 + tx * 8 + 4];
            #pragma unroll
            for (int i = 0; i < 4; i++) {
                o[i][0] = fmaf(a[i], h0.x, o[i][0]);
                o[i][1] = fmaf(a[i], h0.y, o[i][1]);
                o[i][2] = fmaf(a[i], h0.z, o[i][2]);
                o[i][3] = fmaf(a[i], h0.w, o[i][3]);
                o[i][4] = fmaf(a[i], h1.x, o[i][4]);
                o[i][5] = fmaf(a[i], h1.y, o[i][5]);
                o[i][6] = fmaf(a[i], h1.z, o[i][6]);
                o[i][7] = fmaf(a[i], h1.w, o[i][7]);
            }
        }
    }

    // epilogue: optional relu, vectorized store
    #pragma unroll
    for (int i = 0; i < 4; i++) {
        float v[8];
        #pragma unroll
        for (int j = 0; j < 8; j++)
            v[j] = do_relu ? fmaxf(o[i][j], 0.0f) : o[i][j];
        float* dst = &out[((size_t)b * NN + pbase + ty * 4 + i) * DD + tx * 8];
        *(float4*)&dst[0] = make_float4(v[0], v[1], v[2], v[3]);
        *(float4*)&dst[4] = make_float4(v[4], v[5], v[6], v[7]);
    }
}

// ---------------------------------------------------------------------------
extern "C" void kernel_launch(void* const* d_in, const int* in_sizes, int n_in,
                              void* d_out, int out_size)
{
    const float* x  = (const float*)d_in[0];
    const float* ew = (const float*)d_in[1];
    const float* W[3]  = {(const float*)d_in[2], (const float*)d_in[4], (const float*)d_in[6]};
    const float* bb[3] = {(const float*)d_in[3], (const float*)d_in[5], (const float*)d_in[7]};
    float* out = (float*)d_out;

    float *bufA, *bufB, *rn;
    cudaGetSymbolAddress((void**)&bufA, g_bufA);
    cudaGetSymbolAddress((void**)&bufB, g_bufB);
    cudaGetSymbolAddress((void**)&rn, g_rn);

    cudaFuncSetAttribute(linear_norm_kernel,
                         cudaFuncAttributeMaxDynamicSharedMemorySize, SMEM_LIN);
    cudaFuncSetAttribute(fused_agg_kernel,
                         cudaFuncAttributeMaxDynamicSharedMemorySize, SMEM_FUSED);

    const dim3 gl(ROWS_TOT / 64);
    const dim3 gf(NN / 64, NB);

    const float* cur = x;
    for (int l = 0; l < 3; l++) {
        linear_norm_kernel<<<gl, 256, SMEM_LIN>>>(cur, W[l], bb[l], bufA, rn);
        float* dst = (l == 2) ? out : bufB;
        fused_agg_kernel<<<gf, 256, SMEM_FUSED>>>(bufA, rn, ew, dst, (l < 2) ? 1 : 0);
        cur = bufB;
    }
}

// round 3
// speedup vs baseline: 5.5927x; 5.5927x over previous
#include <cuda_runtime.h>
#include <cuda_bf16.h>
#include <cstdint>
#include <math.h>

#define NB 8
#define NN 2048
#define DD 128
#define ROWS_TOT (NB * NN)

// ---------------------------------------------------------------------------
// Global scratch (no allocations allowed)
// ---------------------------------------------------------------------------
__device__ float g_buf[ROWS_TOT * DD];            // fp32 aggregated output (next layer input)
__device__ __nv_bfloat16 g_hhi[ROWS_TOT * DD];    // h split hi  [B*N][128]
__device__ __nv_bfloat16 g_hlo[ROWS_TOT * DD];    // h split lo
__device__ float g_rn[ROWS_TOT];                  // 1/max(||h||,eps)

// ---------------------------------------------------------------------------
// helpers
// ---------------------------------------------------------------------------
__device__ __forceinline__ uint32_t smem_u32(const void* p) {
    uint32_t a;
    asm("{ .reg .u64 t; cvta.to.shared.u64 t, %1; cvt.u32.u64 %0, t; }" : "=r"(a) : "l"(p));
    return a;
}

__device__ __forceinline__ void mma_bf16(float* d, const uint32_t* a, const uint32_t* b) {
    asm volatile(
        "mma.sync.aligned.m16n8k16.row.col.f32.bf16.bf16.f32 "
        "{%0,%1,%2,%3}, {%4,%5,%6,%7}, {%8,%9}, {%0,%1,%2,%3};"
        : "+f"(d[0]), "+f"(d[1]), "+f"(d[2]), "+f"(d[3])
        : "r"(a[0]), "r"(a[1]), "r"(a[2]), "r"(a[3]), "r"(b[0]), "r"(b[1]));
}

__device__ __forceinline__ void ldsm4(uint32_t* r, uint32_t addr) {
    asm volatile("ldmatrix.sync.aligned.m8n8.x4.shared.b16 {%0,%1,%2,%3}, [%4];"
                 : "=r"(r[0]), "=r"(r[1]), "=r"(r[2]), "=r"(r[3]) : "r"(addr));
}
__device__ __forceinline__ void ldsm4t(uint32_t* r, uint32_t addr) {
    asm volatile("ldmatrix.sync.aligned.m8n8.x4.trans.shared.b16 {%0,%1,%2,%3}, [%4];"
                 : "=r"(r[0]), "=r"(r[1]), "=r"(r[2]), "=r"(r[3]) : "r"(addr));
}

__device__ __forceinline__ uint32_t packbf(float a, float b) {
    const uint16_t la = __bfloat16_as_ushort(__float2bfloat16(a));
    const uint16_t lb = __bfloat16_as_ushort(__float2bfloat16(b));
    return ((uint32_t)lb << 16) | la;  // low bits = first (even col)
}

// split two floats into bf16 hi pair + bf16 residual pair
__device__ __forceinline__ void split2(float v0, float v1, uint32_t& hi, uint32_t& lo) {
    const __nv_bfloat16 h0 = __float2bfloat16(v0);
    const __nv_bfloat16 h1 = __float2bfloat16(v1);
    const float r0 = v0 - __bfloat162float(h0);
    const float r1 = v1 - __bfloat162float(h1);
    hi = ((uint32_t)__bfloat16_as_ushort(h1) << 16) | __bfloat16_as_ushort(h0);
    lo = packbf(r0, r1);
}

// ---------------------------------------------------------------------------
// Linear + bias + split to bf16 hi/lo + reciprocal norm   (proven in R1/R2)
// ---------------------------------------------------------------------------
#define SMEM_LIN ((64 * 132 + 128 * 132) * 4)

__global__ __launch_bounds__(256, 2) void linear_norm_kernel(
    const float* __restrict__ in, const float* __restrict__ W, const float* __restrict__ bias,
    __nv_bfloat16* __restrict__ hhi, __nv_bfloat16* __restrict__ hlo, float* __restrict__ rn)
{
    extern __shared__ float sm[];
    float* sx = sm;
    float* sw = sm + 64 * 132;

    const int t = threadIdx.x;
    const int rowbase = blockIdx.x * 64;
    const int f4 = (t & 31) * 4;
    const int r0 = t >> 5;

    #pragma unroll
    for (int r = r0; r < 64; r += 8)
        *(float4*)&sx[r * 132 + f4] = *(const float4*)&in[(size_t)(rowbase + r) * DD + f4];
    #pragma unroll
    for (int r = r0; r < 128; r += 8)
        *(float4*)&sw[r * 132 + f4] = *(const float4*)&W[(size_t)r * DD + f4];
    __syncthreads();

    const int tx = t & 15;
    const int ty = t >> 4;

    float acc[4][8];
    #pragma unroll
    for (int i = 0; i < 4; i++)
        #pragma unroll
        for (int j = 0; j < 8; j++) acc[i][j] = 0.0f;

    #pragma unroll 4
    for (int k = 0; k < DD; k++) {
        float a[4], w[8];
        #pragma unroll
        for (int i = 0; i < 4; i++) a[i] = sx[(ty * 4 + i) * 132 + k];
        #pragma unroll
        for (int j = 0; j < 8; j++) w[j] = sw[k * 132 + tx + 16 * j];
        #pragma unroll
        for (int i = 0; i < 4; i++)
            #pragma unroll
            for (int j = 0; j < 8; j++)
                acc[i][j] = fmaf(a[i], w[j], acc[i][j]);
    }

    float bv[8];
    #pragma unroll
    for (int j = 0; j < 8; j++) bv[j] = bias[tx + 16 * j];

    #pragma unroll
    for (int i = 0; i < 4; i++) {
        float ss = 0.0f;
        #pragma unroll
        for (int j = 0; j < 8; j++) {
            acc[i][j] += bv[j];
            ss = fmaf(acc[i][j], acc[i][j], ss);
        }
        #pragma unroll
        for (int off = 8; off > 0; off >>= 1)
            ss += __shfl_xor_sync(0xffffffffu, ss, off, 16);
        if (tx == 0)
            rn[rowbase + ty * 4 + i] = 1.0f / fmaxf(sqrtf(ss), 1e-12f);
    }

    #pragma unroll
    for (int i = 0; i < 4; i++)
        #pragma unroll
        for (int j = 0; j < 8; j++) {
            const float v = acc[i][j];
            const __nv_bfloat16 h = __float2bfloat16(v);
            const __nv_bfloat16 l = __float2bfloat16(v - __bfloat162float(h));
            const size_t idx = (size_t)(rowbase + ty * 4 + i) * DD + tx + 16 * j;
            hhi[idx] = h;
            hlo[idx] = l;
        }
}

// ---------------------------------------------------------------------------
// Fused flash-style aggregation with mma.sync (HMMA) + bf16 hi/lo splits.
// 256 threads = 8 warps; block = 128 p-rows (16 per warp); q-tiles of 64.
// ---------------------------------------------------------------------------
#define QT 64
#define HQS 136                 // smem row stride in elements (272 B)

__global__ __launch_bounds__(256, 1) void fused_mma_kernel(
    const __nv_bfloat16* __restrict__ hhi, const __nv_bfloat16* __restrict__ hlo,
    const float* __restrict__ rn, const float* __restrict__ ew,
    float* __restrict__ out, int do_relu)
{
    __shared__ __nv_bfloat16 sHqHi[QT * HQS];
    __shared__ __nv_bfloat16 sHqLo[QT * HQS];

    const int t = threadIdx.x;
    const int w = t >> 5;
    const int lane = t & 31;
    const int quad = lane & 3;
    const int gr = lane >> 2;
    const int b = blockIdx.y;
    const int pbase = blockIdx.x * 128;

    const __nv_bfloat16* hhB = hhi + (size_t)b * NN * DD;
    const __nv_bfloat16* hlB = hlo + (size_t)b * NN * DD;
    const float* rnB = rn + (size_t)b * NN;
    const float* ewB = ew + (size_t)b * NN * NN;

    const int prow0 = pbase + w * 16 + gr;
    const int prow1 = prow0 + 8;
    const int ac = quad * 2;

    // ---- A fragments (Hp hi/lo), resident in registers ----
    uint32_t Ahi[8][4], Alo[8][4];
    #pragma unroll
    for (int kc = 0; kc < 8; kc++) {
        Ahi[kc][0] = *(const uint32_t*)&hhB[(size_t)prow0 * DD + kc * 16 + ac];
        Ahi[kc][1] = *(const uint32_t*)&hhB[(size_t)prow1 * DD + kc * 16 + ac];
        Ahi[kc][2] = *(const uint32_t*)&hhB[(size_t)prow0 * DD + kc * 16 + 8 + ac];
        Ahi[kc][3] = *(const uint32_t*)&hhB[(size_t)prow1 * DD + kc * 16 + 8 + ac];
        Alo[kc][0] = *(const uint32_t*)&hlB[(size_t)prow0 * DD + kc * 16 + ac];
        Alo[kc][1] = *(const uint32_t*)&hlB[(size_t)prow1 * DD + kc * 16 + ac];
        Alo[kc][2] = *(const uint32_t*)&hlB[(size_t)prow0 * DD + kc * 16 + 8 + ac];
        Alo[kc][3] = *(const uint32_t*)&hlB[(size_t)prow1 * DD + kc * 16 + 8 + ac];
    }
    const float rp0 = rnB[prow0];
    const float rp1 = rnB[prow1];

    float O[16][4];
    #pragma unroll
    for (int i = 0; i < 16; i++)
        #pragma unroll
        for (int j = 0; j < 4; j++) O[i][j] = 0.0f;

    const uint32_t sHi = smem_u32(sHqHi);
    const uint32_t sLo = smem_u32(sHqLo);
    // per-lane ldmatrix offsets (bytes)
    const uint32_t off1 = (uint32_t)((lane & 7) * (HQS * 2) + (lane >> 3) * 16);   // GEMM1
    const uint32_t off2 = (uint32_t)((lane & 15) * (HQS * 2) + (lane >> 4) * 16);  // GEMM2 (trans)

    for (int qb = 0; qb < NN; qb += QT) {
        __syncthreads();
        // ---- stage Hq tile (64 x 128, hi+lo), 16B per thread x 4 passes ----
        #pragma unroll
        for (int i = 0; i < 4; i++) {
            const int idx = i * 256 + t;
            const int r = idx >> 4, c = idx & 15;
            *(uint4*)((char*)sHqHi + r * (HQS * 2) + c * 16) =
                *(const uint4*)&hhB[(size_t)(qb + r) * DD + c * 8];
            *(uint4*)((char*)sHqLo + r * (HQS * 2) + c * 16) =
                *(const uint4*)&hlB[(size_t)(qb + r) * DD + c * 8];
        }
        __syncthreads();

        // ---- GEMM1: S = AhiBhi + AloBhi + AhiBlo  (16p x 64q per warp) ----
        float S[8][4];
        #pragma unroll
        for (int i = 0; i < 8; i++)
            #pragma unroll
            for (int j = 0; j < 4; j++) S[i][j] = 0.0f;

        #pragma unroll
        for (int kp = 0; kp < 4; kp++) {
            #pragma unroll
            for (int nc = 0; nc < 8; nc++) {
                const uint32_t base = (uint32_t)(nc * 8 * (HQS * 2) + kp * 64);
                uint32_t bh[4], bl[4];
                ldsm4(bh, sHi + base + off1);
                mma_bf16(S[nc], Ahi[2 * kp],     bh + 0);
                mma_bf16(S[nc], Ahi[2 * kp + 1], bh + 2);
                mma_bf16(S[nc], Alo[2 * kp],     bh + 0);
                mma_bf16(S[nc], Alo[2 * kp + 1], bh + 2);
                ldsm4(bl, sLo + base + off1);
                mma_bf16(S[nc], Ahi[2 * kp],     bl + 0);
                mma_bf16(S[nc], Ahi[2 * kp + 1], bl + 2);
            }
        }

        // ---- mask: S *= rp * rq * ew ----
        #pragma unroll
        for (int nc = 0; nc < 8; nc++) {
            const int qcol = qb + nc * 8 + ac;
            const float2 e0 = *(const float2*)&ewB[(size_t)prow0 * NN + qcol];
            const float2 e1 = *(const float2*)&ewB[(size_t)prow1 * NN + qcol];
            const float2 rq = *(const float2*)&rnB[qcol];
            S[nc][0] *= rp0 * rq.x * e0.x;
            S[nc][1] *= rp0 * rq.y * e0.y;
            S[nc][2] *= rp1 * rq.x * e1.x;
            S[nc][3] *= rp1 * rq.y * e1.y;
        }

        // ---- P = split(S) as A fragments (k = q) ----
        uint32_t Phi[4][4], Plo[4][4];
        #pragma unroll
        for (int kc = 0; kc < 4; kc++) {
            split2(S[2 * kc][0],     S[2 * kc][1],     Phi[kc][0], Plo[kc][0]);
            split2(S[2 * kc][2],     S[2 * kc][3],     Phi[kc][1], Plo[kc][1]);
            split2(S[2 * kc + 1][0], S[2 * kc + 1][1], Phi[kc][2], Plo[kc][2]);
            split2(S[2 * kc + 1][2], S[2 * kc + 1][3], Phi[kc][3], Plo[kc][3]);
        }

        // ---- GEMM2: O += PhiBhi + PloBhi + PhiBlo  (B = Hq via ldmatrix.trans) ----
        #pragma unroll
        for (int kc = 0; kc < 4; kc++) {
            #pragma unroll
            for (int np = 0; np < 8; np++) {
                const uint32_t base = (uint32_t)(kc * 16 * (HQS * 2) + np * 32);
                uint32_t bh[4], bl[4];
                ldsm4t(bh, sHi + base + off2);
                mma_bf16(O[2 * np],     Phi[kc], bh + 0);
                mma_bf16(O[2 * np + 1], Phi[kc], bh + 2);
                mma_bf16(O[2 * np],     Plo[kc], bh + 0);
                mma_bf16(O[2 * np + 1], Plo[kc], bh + 2);
                ldsm4t(bl, sLo + base + off2);
                mma_bf16(O[2 * np],     Phi[kc], bl + 0);
                mma_bf16(O[2 * np + 1], Phi[kc], bl + 2);
            }
        }
    }

    // ---- epilogue: relu + store ----
    float* outB = out + (size_t)b * NN * DD;
    #pragma unroll
    for (int nc = 0; nc < 16; nc++) {
        float v0 = O[nc][0], v1 = O[nc][1], v2 = O[nc][2], v3 = O[nc][3];
        if (do_relu) {
            v0 = fmaxf(v0, 0.0f); v1 = fmaxf(v1, 0.0f);
            v2 = fmaxf(v2, 0.0f); v3 = fmaxf(v3, 0.0f);
        }
        *(float2*)&outB[(size_t)prow0 * DD + nc * 8 + ac] = make_float2(v0, v1);
        *(float2*)&outB[(size_t)prow1 * DD + nc * 8 + ac] = make_float2(v2, v3);
    }
}

// ---------------------------------------------------------------------------
extern "C" void kernel_launch(void* const* d_in, const int* in_sizes, int n_in,
                              void* d_out, int out_size)
{
    const float* x  = (const float*)d_in[0];
    const float* ew = (const float*)d_in[1];
    const float* W[3]  = {(const float*)d_in[2], (const float*)d_in[4], (const float*)d_in[6]};
    const float* bb[3] = {(const float*)d_in[3], (const float*)d_in[5], (const float*)d_in[7]};
    float* out = (float*)d_out;

    float *buf, *rn;
    __nv_bfloat16 *hhi, *hlo;
    cudaGetSymbolAddress((void**)&buf, g_buf);
    cudaGetSymbolAddress((void**)&rn, g_rn);
    cudaGetSymbolAddress((void**)&hhi, g_hhi);
    cudaGetSymbolAddress((void**)&hlo, g_hlo);

    cudaFuncSetAttribute(linear_norm_kernel,
                         cudaFuncAttributeMaxDynamicSharedMemorySize, SMEM_LIN);

    const dim3 gl(ROWS_TOT / 64);
    const dim3 gf(NN / 128, NB);

    const float* cur = x;
    for (int l = 0; l < 3; l++) {
        linear_norm_kernel<<<gl, 256, SMEM_LIN>>>(cur, W[l], bb[l], hhi, hlo, rn);
        float* dst = (l == 2) ? out : buf;
        fused_mma_kernel<<<gf, 256>>>(hhi, hlo, rn, ew, dst, (l < 2) ? 1 : 0);
        cur = buf;
    }
}